// round 17
// baseline (speedup 1.0000x reference)
#include <cuda_runtime.h>
#include <math.h>
#include <stdint.h>

// Problem dims (fixed by setup_inputs)
#define MAXN 100000
#define D2 50
#define D3 15
#define D5 10
#define NC 6

// ---------------- device scratch ----------------
// per-node record: 15 accum floats + count in slot 15 (16 floats = 64B)
// Zero-initialized at module load; zero_kernel (after graph_kernel) restores
// the invariant for the next graph replay.
__device__ __align__(16) float g_x2sum[MAXN * 16];

__device__ __forceinline__ void red4(float* p, float a, float b, float c, float d) {
    asm volatile("red.global.add.v4.f32 [%0], {%1, %2, %3, %4};"
                 :: "l"(p), "f"(a), "f"(b), "f"(c), "f"(d) : "memory");
}

// ---------------- zero accumulators (runs after graph_kernel) -------------
__global__ void zero_kernel(int N) {
    int tid = blockIdx.x * blockDim.x + threadIdx.x;
    int stride = gridDim.x * blockDim.x;
    int total = N * 4;
    float4 z = make_float4(0.f, 0.f, 0.f, 0.f);
    float4* p = reinterpret_cast<float4*>(g_x2sum);
    for (int t = tid; t < total; t += stride) p[t] = z;
}

// ---------------- tf32 helpers ----------------
__device__ __forceinline__ unsigned tf32_of(float v) {
    unsigned r;
    asm("cvt.rna.tf32.f32 %0, %1;" : "=r"(r) : "f"(v));
    return r;
}
__device__ __forceinline__ void tf32_split(float v, unsigned& hi, unsigned& lo) {
    hi = tf32_of(v);
    lo = tf32_of(v - __uint_as_float(hi));
}
__device__ __forceinline__ void mma8(float& c0, float& c1, float& c2, float& c3,
                                     unsigned a0, unsigned a1, unsigned a2, unsigned a3,
                                     unsigned b0, unsigned b1) {
    asm volatile(
        "mma.sync.aligned.m16n8k8.row.col.f32.tf32.tf32.f32 "
        "{%0,%1,%2,%3}, {%4,%5,%6,%7}, {%8,%9}, {%0,%1,%2,%3};"
        : "+f"(c0), "+f"(c1), "+f"(c2), "+f"(c3)
        : "r"(a0), "r"(a1), "r"(a2), "r"(a3), "r"(b0), "r"(b1));
}
// 3xTF32: D += Ahi*Bhi + Ahi*Blo + Alo*Bhi
__device__ __forceinline__ void mma3(float& c0, float& c1, float& c2, float& c3,
                                     const unsigned* ah, const unsigned* al, uint4 b) {
    mma8(c0, c1, c2, c3, ah[0], ah[1], ah[2], ah[3], b.x, b.z);
    mma8(c0, c1, c2, c3, ah[0], ah[1], ah[2], ah[3], b.y, b.w);
    mma8(c0, c1, c2, c3, al[0], al[1], al[2], al[3], b.x, b.z);
}

// Stage a [K x N] row-major weight matrix into m16n8k8 B-fragment order:
// dst[(ks*NT + nt)*32 + lane] = {b0hi, b0lo, b1hi, b1lo}
// where b0 = W[ks*8 + t][nt*8 + g], b1 = W[ks*8 + t + 4][nt*8 + g].
__device__ __forceinline__ void stage_frags(uint4* dst, const float* W,
                                            int K, int N, int KS, int NT,
                                            int tid, int nthreads) {
    int total = KS * NT * 32;
    for (int idx = tid; idx < total; idx += nthreads) {
        int ks = idx / (NT * 32);
        int rem = idx % (NT * 32);
        int nt = rem / 32;
        int l = rem % 32;
        int g = l >> 2, t = l & 3;
        int n = nt * 8 + g;
        int k0 = ks * 8 + t;
        int k1 = k0 + 4;
        float w0 = (k0 < K && n < N) ? W[k0 * N + n] : 0.0f;
        float w1 = (k1 < K && n < N) ? W[k1 * N + n] : 0.0f;
        unsigned h0, l0, h1, l1;
        tf32_split(w0, h0, l0);
        tf32_split(w1, h1, l1);
        dst[idx] = make_uint4(h0, l0, h1, l1);
    }
}

// ---------------- edge kernel: tensor-core (3xTF32 mma.sync) --------------
// 2 warps/block; each warp processes 16-edge tiles (grid-stride).
#define EW_WARPS 2
#define SIN_STRIDE 20   // bank-clean for frag reads (g*20 mod 32 distinct)
#define SH_STRIDE  60   // bank-clean (g*60 mod 32 = {0,28,24,20,16,12,8,4})

__global__ void __launch_bounds__(64)
edge_mma_kernel(
    const float* __restrict__ x,
    const int* __restrict__ row,
    const int* __restrict__ col,
    const float* __restrict__ ea,
    const float* __restrict__ ew1, const float* __restrict__ eb1,
    const float* __restrict__ ew2, const float* __restrict__ eb2,
    const float* __restrict__ nw1, const float* __restrict__ nb1,
    const float* __restrict__ nw2, const float* __restrict__ nb2,
    int E)
{
    // fragment-ordered weights (hi/lo packed)
    __shared__ uint4 s_ew1[2 * 7 * 32];   // K=9 ->16 (2 ks), N=50->56 (7 nt)
    __shared__ uint4 s_ew2[7 * 2 * 32];   // K=50->56, N=15->16
    __shared__ uint4 s_nw1[3 * 7 * 32];   // K=18->24, N=50->56
    __shared__ uint4 s_nw2[7 * 2 * 32];   // K=50->56, N=15->16
    __shared__ float s_eb1[56], s_eb2[16], s_nb1[56], s_nb2[16];
    // per-warp scratch
    __shared__ float s_in[EW_WARPS][16 * SIN_STRIDE];  // inputs; reused as outputs
    __shared__ float s_h [EW_WARPS][16 * SH_STRIDE];   // hidden / node-input
    __shared__ int   s_ridx[EW_WARPS][16];

    int tid = threadIdx.x;
    int nth = blockDim.x;
    stage_frags(s_ew1, ew1,  9, D2, 2, 7, tid, nth);
    stage_frags(s_ew2, ew2, D2, D3, 7, 2, tid, nth);
    stage_frags(s_nw1, nw1, 18, D2, 3, 7, tid, nth);
    stage_frags(s_nw2, nw2, D2, D3, 7, 2, tid, nth);
    for (int t = tid; t < 56; t += nth) s_eb1[t] = (t < D2) ? eb1[t] : 0.0f;
    for (int t = tid; t < 16; t += nth) s_eb2[t] = (t < D3) ? eb2[t] : 0.0f;
    for (int t = tid; t < 56; t += nth) s_nb1[t] = (t < D2) ? nb1[t] : 0.0f;
    for (int t = tid; t < 16; t += nth) s_nb2[t] = (t < D3) ? nb2[t] : 0.0f;
    __syncthreads();

    int warp = tid >> 5;
    int lane = tid & 31;
    int g = lane >> 2, t4 = lane & 3;
    float* sin = s_in[warp];
    float* sh  = s_h[warp];
    int*   sr  = s_ridx[warp];

    int nTiles = (E + 15) / 16;
    for (int tile = blockIdx.x * EW_WARPS + warp; tile < nTiles;
         tile += gridDim.x * EW_WARPS) {
        int e0 = tile * 16;

        // ---- gather 16 edges (lanes 0-15) ----
        if (lane < 16) {
            int et = e0 + lane;
            float v[9];
            int rr = 0;
            if (et < E) {
                rr = row[et];
                int cc = col[et];
                v[0] = x[3 * rr + 0]; v[1] = x[3 * rr + 1]; v[2] = x[3 * rr + 2];
                v[3] = x[3 * cc + 0]; v[4] = x[3 * cc + 1]; v[5] = x[3 * cc + 2];
                v[6] = ea[3 * et + 0]; v[7] = ea[3 * et + 1]; v[8] = ea[3 * et + 2];
            } else {
                #pragma unroll
                for (int i = 0; i < 9; ++i) v[i] = 0.0f;
            }
            sr[lane] = rr;
            #pragma unroll
            for (int i = 0; i < 9; ++i) sin[lane * SIN_STRIDE + i] = v[i];
            #pragma unroll
            for (int i = 9; i < 16; ++i) sin[lane * SIN_STRIDE + i] = 0.0f;
        }
        __syncwarp();

        // ================= EDGE MLP layer 1: [16x16] @ [16x56] ============
        unsigned aH[2][4], aL[2][4];
        #pragma unroll
        for (int ks = 0; ks < 2; ++ks) {
            float v0 = sin[g * SIN_STRIDE + ks * 8 + t4];
            float v1 = sin[(g + 8) * SIN_STRIDE + ks * 8 + t4];
            float v2 = sin[g * SIN_STRIDE + ks * 8 + t4 + 4];
            float v3 = sin[(g + 8) * SIN_STRIDE + ks * 8 + t4 + 4];
            tf32_split(v0, aH[ks][0], aL[ks][0]);
            tf32_split(v1, aH[ks][1], aL[ks][1]);
            tf32_split(v2, aH[ks][2], aL[ks][2]);
            tf32_split(v3, aH[ks][3], aL[ks][3]);
        }
        #pragma unroll
        for (int nt = 0; nt < 7; ++nt) {
            float c0 = s_eb1[nt * 8 + 2 * t4];
            float c1 = s_eb1[nt * 8 + 2 * t4 + 1];
            float c2 = c0, c3 = c1;
            #pragma unroll
            for (int ks = 0; ks < 2; ++ks)
                mma3(c0, c1, c2, c3, aH[ks], aL[ks], s_ew1[(ks * 7 + nt) * 32 + lane]);
            c0 = fmaxf(c0, 0.f); c1 = fmaxf(c1, 0.f);
            c2 = fmaxf(c2, 0.f); c3 = fmaxf(c3, 0.f);
            sh[g * SH_STRIDE + nt * 8 + 2 * t4]           = c0;
            sh[g * SH_STRIDE + nt * 8 + 2 * t4 + 1]       = c1;
            sh[(g + 8) * SH_STRIDE + nt * 8 + 2 * t4]     = c2;
            sh[(g + 8) * SH_STRIDE + nt * 8 + 2 * t4 + 1] = c3;
        }
        __syncwarp();

        // ================= EDGE MLP layer 2: [16x56] @ [56x16] ============
        unsigned a7H[7][4], a7L[7][4];
        #pragma unroll
        for (int ks = 0; ks < 7; ++ks) {
            float v0 = sh[g * SH_STRIDE + ks * 8 + t4];
            float v1 = sh[(g + 8) * SH_STRIDE + ks * 8 + t4];
            float v2 = sh[g * SH_STRIDE + ks * 8 + t4 + 4];
            float v3 = sh[(g + 8) * SH_STRIDE + ks * 8 + t4 + 4];
            tf32_split(v0, a7H[ks][0], a7L[ks][0]);
            tf32_split(v1, a7H[ks][1], a7L[ks][1]);
            tf32_split(v2, a7H[ks][2], a7L[ks][2]);
            tf32_split(v3, a7H[ks][3], a7L[ks][3]);
        }
        __syncwarp();   // all h reads done; sh becomes node-input buffer

        // node input cols: 0-2 = x[col], 3-17 = e2, 18-23 = 0
        if (lane < 16) {
            sh[lane * SH_STRIDE + 0] = sin[lane * SIN_STRIDE + 3];
            sh[lane * SH_STRIDE + 1] = sin[lane * SIN_STRIDE + 4];
            sh[lane * SH_STRIDE + 2] = sin[lane * SIN_STRIDE + 5];
            #pragma unroll
            for (int cz = 18; cz < 24; ++cz) sh[lane * SH_STRIDE + cz] = 0.0f;
        }
        #pragma unroll
        for (int nt = 0; nt < 2; ++nt) {
            float c0 = s_eb2[nt * 8 + 2 * t4];
            float c1 = s_eb2[nt * 8 + 2 * t4 + 1];
            float c2 = c0, c3 = c1;
            #pragma unroll
            for (int ks = 0; ks < 7; ++ks)
                mma3(c0, c1, c2, c3, a7H[ks], a7L[ks], s_ew2[(ks * 2 + nt) * 32 + lane]);
            // e2 goes to node-input cols 3 + (nt*8 + 2t {,+1})
            sh[g * SH_STRIDE + 3 + nt * 8 + 2 * t4]           = c0;
            sh[g * SH_STRIDE + 3 + nt * 8 + 2 * t4 + 1]       = c1;
            sh[(g + 8) * SH_STRIDE + 3 + nt * 8 + 2 * t4]     = c2;
            sh[(g + 8) * SH_STRIDE + 3 + nt * 8 + 2 * t4 + 1] = c3;
        }
        __syncwarp();

        // ================= NODE MLP layer 1: [16x24] @ [24x56] ============
        unsigned a3H[3][4], a3L[3][4];
        #pragma unroll
        for (int ks = 0; ks < 3; ++ks) {
            float v0 = sh[g * SH_STRIDE + ks * 8 + t4];
            float v1 = sh[(g + 8) * SH_STRIDE + ks * 8 + t4];
            float v2 = sh[g * SH_STRIDE + ks * 8 + t4 + 4];
            float v3 = sh[(g + 8) * SH_STRIDE + ks * 8 + t4 + 4];
            tf32_split(v0, a3H[ks][0], a3L[ks][0]);
            tf32_split(v1, a3H[ks][1], a3L[ks][1]);
            tf32_split(v2, a3H[ks][2], a3L[ks][2]);
            tf32_split(v3, a3H[ks][3], a3L[ks][3]);
        }
        __syncwarp();   // node-input reads done; sh becomes h2 buffer
        #pragma unroll
        for (int nt = 0; nt < 7; ++nt) {
            float c0 = s_nb1[nt * 8 + 2 * t4];
            float c1 = s_nb1[nt * 8 + 2 * t4 + 1];
            float c2 = c0, c3 = c1;
            #pragma unroll
            for (int ks = 0; ks < 3; ++ks)
                mma3(c0, c1, c2, c3, a3H[ks], a3L[ks], s_nw1[(ks * 7 + nt) * 32 + lane]);
            c0 = fmaxf(c0, 0.f); c1 = fmaxf(c1, 0.f);
            c2 = fmaxf(c2, 0.f); c3 = fmaxf(c3, 0.f);
            sh[g * SH_STRIDE + nt * 8 + 2 * t4]           = c0;
            sh[g * SH_STRIDE + nt * 8 + 2 * t4 + 1]       = c1;
            sh[(g + 8) * SH_STRIDE + nt * 8 + 2 * t4]     = c2;
            sh[(g + 8) * SH_STRIDE + nt * 8 + 2 * t4 + 1] = c3;
        }
        __syncwarp();

        // ================= NODE MLP layer 2: [16x56] @ [56x16] ============
        #pragma unroll
        for (int ks = 0; ks < 7; ++ks) {
            float v0 = sh[g * SH_STRIDE + ks * 8 + t4];
            float v1 = sh[(g + 8) * SH_STRIDE + ks * 8 + t4];
            float v2 = sh[g * SH_STRIDE + ks * 8 + t4 + 4];
            float v3 = sh[(g + 8) * SH_STRIDE + ks * 8 + t4 + 4];
            tf32_split(v0, a7H[ks][0], a7L[ks][0]);
            tf32_split(v1, a7H[ks][1], a7L[ks][1]);
            tf32_split(v2, a7H[ks][2], a7L[ks][2]);
            tf32_split(v3, a7H[ks][3], a7L[ks][3]);
        }
        __syncwarp();
        #pragma unroll
        for (int nt = 0; nt < 2; ++nt) {
            float c0 = s_nb2[nt * 8 + 2 * t4];
            float c1 = s_nb2[nt * 8 + 2 * t4 + 1];
            float c2 = c0, c3 = c1;
            #pragma unroll
            for (int ks = 0; ks < 7; ++ks)
                mma3(c0, c1, c2, c3, a7H[ks], a7L[ks], s_nw2[(ks * 2 + nt) * 32 + lane]);
            // outputs to sin (reused; stride 20, cols 0-15)
            sin[g * SIN_STRIDE + nt * 8 + 2 * t4]           = c0;
            sin[g * SIN_STRIDE + nt * 8 + 2 * t4 + 1]       = c1;
            sin[(g + 8) * SIN_STRIDE + nt * 8 + 2 * t4]     = c2;
            sin[(g + 8) * SIN_STRIDE + nt * 8 + 2 * t4 + 1] = c3;
        }
        __syncwarp();

        // ---- scatter (lanes 0-15): 15 vals + count in slot 15 ----
        if (lane < 16 && (e0 + lane) < E) {
            const float* o = &sin[lane * SIN_STRIDE];
            float* dst = &g_x2sum[(size_t)sr[lane] * 16];
            red4(dst + 0,  o[0],  o[1],  o[2],  o[3]);
            red4(dst + 4,  o[4],  o[5],  o[6],  o[7]);
            red4(dst + 8,  o[8],  o[9],  o[10], o[11]);
            red4(dst + 12, o[12], o[13], o[14], 1.0f);
        }
        __syncwarp();
    }
}

// ---------------- graph kernel: per-graph reduce + PARALLEL head ----------
#define SG_GW1 0
#define SG_GB1 (SG_GW1 + 16 * D2)
#define SG_GW2 (SG_GB1 + D2)
#define SG_GB2 (SG_GW2 + D2 * D3)
#define SG_F1W (SG_GB2 + D3)
#define SG_F1B (SG_F1W + D3 * D5)
#define SG_BNG (SG_F1B + D5)
#define SG_BNB (SG_BNG + D5)
#define SG_F2W (SG_BNB + D5)
#define SG_F2B (SG_F2W + D5 * NC)
#define SG_TOTAL (SG_F2B + NC)

__device__ __forceinline__ int lbound(const int* a, int n, int key) {
    int lo = 0, hi = n;
    while (lo < hi) { int m = (lo + hi) >> 1; if (a[m] < key) lo = m + 1; else hi = m; }
    return lo;
}

__global__ void __launch_bounds__(256)
graph_kernel(
    const int* __restrict__ batch,
    const float* __restrict__ u,
    const float* __restrict__ gw1, const float* __restrict__ gb1,
    const float* __restrict__ gw2, const float* __restrict__ gb2,
    const float* __restrict__ fc1w, const float* __restrict__ fc1b,
    const float* __restrict__ bng, const float* __restrict__ bnb,
    const float* __restrict__ fc2w, const float* __restrict__ fc2b,
    float* __restrict__ out, int N)
{
    __shared__ float swt[SG_TOTAL];
    __shared__ float sred[8][30];
    __shared__ int sse[2];
    __shared__ float sin16[16];
    __shared__ float szsum[16];
    __shared__ float shg[D2];
    __shared__ float sg[16];
    __shared__ float sh1[D5 + 2];
    __shared__ float slse[1];

    int tid = threadIdx.x;
    for (int t = tid; t < 16 * D2; t += blockDim.x) swt[SG_GW1 + t] = gw1[t];
    for (int t = tid; t < D2; t += blockDim.x) swt[SG_GB1 + t] = gb1[t];
    for (int t = tid; t < D2 * D3; t += blockDim.x) swt[SG_GW2 + t] = gw2[t];
    for (int t = tid; t < D3; t += blockDim.x) swt[SG_GB2 + t] = gb2[t];
    for (int t = tid; t < D3 * D5; t += blockDim.x) swt[SG_F1W + t] = fc1w[t];
    for (int t = tid; t < D5; t += blockDim.x) {
        swt[SG_F1B + t] = fc1b[t];
        swt[SG_BNG + t] = bng[t];
        swt[SG_BNB + t] = bnb[t];
    }
    for (int t = tid; t < D5 * NC; t += blockDim.x) swt[SG_F2W + t] = fc2w[t];
    for (int t = tid; t < NC; t += blockDim.x) swt[SG_F2B + t] = fc2b[t];

    int b = blockIdx.x;
    if (tid == 0) {
        sse[0] = lbound(batch, N, b);
        sse[1] = lbound(batch, N, b + 1);
    }
    __syncthreads();
    int s = sse[0], epos = sse[1];
    int nnodes = epos - s;
    float cntf = (float)nnodes;
    float invc = 1.0f / fmaxf(cntf, 1.0f);
    float invg = 1.0f / (cntf + 1.0f);

    float acc[30];
    #pragma unroll
    for (int k = 0; k < 30; ++k) acc[k] = 0.0f;

    for (int n = s + tid; n < epos; n += blockDim.x) {
        const float4* p = reinterpret_cast<const float4*>(&g_x2sum[(size_t)n * 16]);
        float4 a0 = p[0], a1 = p[1], a2 = p[2], a3 = p[3];
        float vv[15] = { a0.x, a0.y, a0.z, a0.w, a1.x, a1.y, a1.z, a1.w,
                         a2.x, a2.y, a2.z, a2.w, a3.x, a3.y, a3.z };
        float cnt = a3.w;
        float inv = 1.0f / fmaxf(cnt, 1.0f);
        #pragma unroll
        for (int k = 0; k < 15; ++k) {
            float t = vv[k] * inv;
            acc[k] += t;
            acc[15 + k] += fmaxf(t, 0.0f);
        }
    }

    #pragma unroll
    for (int k = 0; k < 30; ++k) {
        float v = acc[k];
        #pragma unroll
        for (int off = 16; off > 0; off >>= 1)
            v += __shfl_down_sync(0xFFFFFFFF, v, off);
        acc[k] = v;
    }
    int wid = tid >> 5, lid = tid & 31;
    if (lid == 0) {
        #pragma unroll
        for (int k = 0; k < 30; ++k) sred[wid][k] = acc[k];
    }
    __syncthreads();

    if (tid < 15) {
        float v = 0.0f;
        #pragma unroll
        for (int w = 0; w < 8; ++w) v += sred[w][tid];
        sin16[1 + tid] = v * invc;
    } else if (tid >= 16 && tid < 31) {
        int k = tid - 16;
        float v = 0.0f;
        #pragma unroll
        for (int w = 0; w < 8; ++w) v += sred[w][15 + k];
        szsum[k] = v;
    } else if (tid == 15) {
        sin16[0] = u[b];
    }
    __syncthreads();

    if (tid < D2) {
        float v = swt[SG_GB1 + tid];
        #pragma unroll
        for (int i = 0; i < 16; ++i)
            v += sin16[i] * swt[SG_GW1 + i * D2 + tid];
        shg[tid] = fmaxf(v, 0.0f);
    }
    __syncthreads();

    if (tid < D3) {
        float v = swt[SG_GB2 + tid];
        #pragma unroll
        for (int j = 0; j < D2; ++j)
            v += shg[j] * swt[SG_GW2 + j * D3 + tid];
        sg[tid] = (szsum[tid] + fmaxf(v, 0.0f)) * invg;
    }
    __syncthreads();

    if (tid < D5) {
        float v = swt[SG_F1B + tid];
        #pragma unroll
        for (int k = 0; k < D3; ++k)
            v += sg[k] * swt[SG_F1W + k * D5 + tid];
        float rs = rsqrtf(1.0f + 1e-5f);
        sh1[tid] = fmaxf(v * (swt[SG_BNG + tid] * rs) + swt[SG_BNB + tid], 0.0f);
    }
    __syncthreads();

    if (tid < NC) {
        float v = swt[SG_F2B + tid];
        #pragma unroll
        for (int m = 0; m < D5; ++m)
            v += sh1[m] * swt[SG_F2W + m * NC + tid];
        sg[tid] = v;
    }
    __syncthreads();

    if (tid == 0) {
        float mx = sg[0];
        #pragma unroll
        for (int q = 1; q < NC; ++q) mx = fmaxf(mx, sg[q]);
        float ssum = 0.0f;
        #pragma unroll
        for (int q = 0; q < NC; ++q) ssum += expf(sg[q] - mx);
        slse[0] = mx + logf(ssum);
    }
    __syncthreads();
    if (tid < NC)
        out[b * NC + tid] = sg[tid] - slse[0];
}

// ---------------- launch ----------------
extern "C" void kernel_launch(void* const* d_in, const int* in_sizes, int n_in,
                              void* d_out, int out_size) {
    const float* x     = (const float*)d_in[0];
    const int*   ei    = (const int*)d_in[1];
    const float* ea    = (const float*)d_in[2];
    const float* u     = (const float*)d_in[3];
    const int*   batch = (const int*)d_in[4];
    const float* ew1   = (const float*)d_in[5];
    const float* eb1   = (const float*)d_in[6];
    const float* ew2   = (const float*)d_in[7];
    const float* eb2   = (const float*)d_in[8];
    const float* nw1   = (const float*)d_in[9];
    const float* nb1   = (const float*)d_in[10];
    const float* nw2   = (const float*)d_in[11];
    const float* nb2   = (const float*)d_in[12];
    const float* gw1   = (const float*)d_in[13];
    const float* gb1   = (const float*)d_in[14];
    const float* gw2   = (const float*)d_in[15];
    const float* gb2   = (const float*)d_in[16];
    const float* fc1w  = (const float*)d_in[17];
    const float* fc1b  = (const float*)d_in[18];
    const float* bng   = (const float*)d_in[19];
    const float* bnb   = (const float*)d_in[20];
    const float* fc2w  = (const float*)d_in[21];
    const float* fc2b  = (const float*)d_in[22];
    float* out = (float*)d_out;

    int N = in_sizes[0] / 3;   // nodes
    int E = in_sizes[1] / 2;   // edges
    int B = in_sizes[3];       // graphs

    const int* row = ei;
    const int* col = ei + E;

    // invariant: g_x2sum is zero at entry (module-load init / trailing zero)
    edge_mma_kernel<<<740, 64>>>(x, row, col, ea,
                                 ew1, eb1, ew2, eb2,
                                 nw1, nb1, nw2, nb2, E);

    graph_kernel<<<B, 256>>>(batch, u,
                             gw1, gb1, gw2, gb2,
                             fc1w, fc1b, bng, bnb, fc2w, fc2b, out, N);

    // restore the zero invariant for the next replay
    zero_kernel<<<512, 256>>>(N);
}